// round 8
// baseline (speedup 1.0000x reference)
#include <cuda_runtime.h>
#include <cuda_bf16.h>
#include <cstdint>

// ScaleLayer: y[b,d] = x[b,d] * exp(diag[d]);  second output = raw diag.
// x: [16384, 4096] fp32 row-major; diag: [4096] fp32.
//
// R8: identical global access set to the measured-best R7 (single kernel,
// exact-cover, loop-free, 4 front-batched LDG.128/thread at 64MB stride,
// plain LDG/STG, inline exp hidden under memory stalls), but 512-thread
// CTAs (8192 blocks): half the block prologues / wave-sched events at the
// same occupancy (16 warps x 2 CTAs/SM = same 32-warp ceiling).
// Kernel is at the HBM streaming roofline (~6.5 TB/s, 82.5% DRAM).

#define D_DIM 4096
#define B_DIM 16384
#define THREADS 512

// total4 = 16,777,216 float4.  grid*block = 4,194,304 threads = total4/4.
// Thread j handles {j, j+S, j+2S, j+3S}, S = total threads: exact cover.
// S is a multiple of D_DIM/4, so all four elements share one float4 column.
__global__ void __launch_bounds__(THREADS)
scale_kernel(const float4* __restrict__ x,
             const float4* __restrict__ diag4,
             float4* __restrict__ y,
             float4* __restrict__ tail,   // d_out + B*D (raw diag echo)
             int write_tail) {
    constexpr int S = (B_DIM * D_DIM) / 4 / 4;     // 4,194,304

    const int j  = blockIdx.x * THREADS + threadIdx.x;
    const int j0 = j;
    const int j1 = j + S;
    const int j2 = j + 2 * S;
    const int j3 = j + 3 * S;
    const int col4 = j & (D_DIM / 4 - 1);

    // Front-batched independent loads (MLP=4) + the 16B diag load (L1-hot).
    float4 v0 = x[j0];
    float4 v1 = x[j1];
    float4 v2 = x[j2];
    float4 v3 = x[j3];
    float4 d  = diag4[col4];

    // Raw diag echo: threads j<1024 give col4 == j -> exact cover of the
    // 1024-float4 tail by the first two blocks.
    if (write_tail && j < (D_DIM / 4)) tail[j] = d;

    // exp() inline -- MUFU work overlapped with memory stalls
    // (measured: issue 8%->14%, DRAM% unchanged).
    float4 e;
    e.x = expf(d.x);
    e.y = expf(d.y);
    e.z = expf(d.z);
    e.w = expf(d.w);

    v0.x *= e.x; v0.y *= e.y; v0.z *= e.z; v0.w *= e.w;
    v1.x *= e.x; v1.y *= e.y; v1.z *= e.z; v1.w *= e.w;
    v2.x *= e.x; v2.y *= e.y; v2.z *= e.z; v2.w *= e.w;
    v3.x *= e.x; v3.y *= e.y; v3.z *= e.z; v3.w *= e.w;

    y[j0] = v0;
    y[j1] = v1;
    y[j2] = v2;
    y[j3] = v3;
}

extern "C" void kernel_launch(void* const* d_in, const int* in_sizes, int n_in,
                              void* d_out, int out_size) {
    const float* x    = (const float*)d_in[0];
    const float* diag = (const float*)d_in[1];
    float* out = (float*)d_out;

    const long long n_main = (long long)B_DIM * D_DIM;
    const int write_tail = (out_size > n_main) ? 1 : 0;

    // 16,777,216 float4 / (512 thr * 4 per thread) = 8192 CTAs, exact.
    scale_kernel<<<8192, THREADS>>>((const float4*)x,
                                    (const float4*)diag,
                                    (float4*)out,
                                    (float4*)(out + n_main),
                                    write_tail);
}

// round 9
// speedup vs baseline: 1.0020x; 1.0020x over previous
#include <cuda_runtime.h>
#include <cuda_bf16.h>
#include <cstdint>

// ScaleLayer: y[b,d] = x[b,d] * exp(diag[d]);  second output = raw diag.
// x: [16384, 4096] fp32 row-major; diag: [4096] fp32.
//
// FINAL (R7 config, measured best: kernel 74.18us @ 82.5% DRAM / 6.54 TB/s,
// total 82.0us). The kernel is pinned at the B300 HBM/LTS streaming ceiling
// for 512 MiB of mandatory read+write traffic; 7 structural variants span
// only 74.2-77.5us. Design:
//   - single kernel (a separate exp-prologue node cost ~2us of graph
//     serialization); exp() of each thread's 4 diag entries computed inline,
//     fully hidden under memory stalls (issue 8%->14%, DRAM% unchanged)
//   - exact-cover, loop-free: thread j handles {j, j+S, j+2S, j+3S} float4s
//     (S = total threads), 4 front-batched independent LDG.128 (MLP=4)
//   - plain LDG/STG (ldcs/stcs measured neutral-to-negative)
//   - 16384 CTAs x 256 threads, 32 regs, ~79% occupancy
//   - diag echo: threads j<1024 write tail[j] (col4==j there), exact cover

#define D_DIM 4096
#define B_DIM 16384

__global__ void __launch_bounds__(256)
scale_kernel(const float4* __restrict__ x,
             const float4* __restrict__ diag4,
             float4* __restrict__ y,
             float4* __restrict__ tail,   // d_out + B*D (raw diag echo)
             int write_tail) {
    constexpr int S = (B_DIM * D_DIM) / 4 / 4;     // 4,194,304

    const int j  = blockIdx.x * blockDim.x + threadIdx.x;
    const int j0 = j;
    const int j1 = j + S;
    const int j2 = j + 2 * S;
    const int j3 = j + 3 * S;
    const int col4 = j & (D_DIM / 4 - 1);

    // Front-batched independent loads (MLP=4) + the 16B diag load (L1-hot).
    float4 v0 = x[j0];
    float4 v1 = x[j1];
    float4 v2 = x[j2];
    float4 v3 = x[j3];
    float4 d  = diag4[col4];

    // Raw diag echo: threads j<1024 give col4 == j -> exact cover of the
    // 1024-float4 tail by blocks 0..3.
    if (write_tail && j < (D_DIM / 4)) tail[j] = d;

    // exp() inline -- MUFU work overlapped with memory stalls.
    float4 e;
    e.x = expf(d.x);
    e.y = expf(d.y);
    e.z = expf(d.z);
    e.w = expf(d.w);

    v0.x *= e.x; v0.y *= e.y; v0.z *= e.z; v0.w *= e.w;
    v1.x *= e.x; v1.y *= e.y; v1.z *= e.z; v1.w *= e.w;
    v2.x *= e.x; v2.y *= e.y; v2.z *= e.z; v2.w *= e.w;
    v3.x *= e.x; v3.y *= e.y; v3.z *= e.z; v3.w *= e.w;

    y[j0] = v0;
    y[j1] = v1;
    y[j2] = v2;
    y[j3] = v3;
}

extern "C" void kernel_launch(void* const* d_in, const int* in_sizes, int n_in,
                              void* d_out, int out_size) {
    const float* x    = (const float*)d_in[0];
    const float* diag = (const float*)d_in[1];
    float* out = (float*)d_out;

    const long long n_main = (long long)B_DIM * D_DIM;
    const int write_tail = (out_size > n_main) ? 1 : 0;

    // 16,777,216 float4 / (256 thr * 4 per thread) = 16384 CTAs, exact.
    scale_kernel<<<16384, 256>>>((const float4*)x,
                                 (const float4*)diag,
                                 (float4*)out,
                                 (float4*)(out + n_main),
                                 write_tail);
}